// round 16
// baseline (speedup 1.0000x reference)
#include <cuda_runtime.h>
#include <cuda_fp16.h>
#include <math.h>
#include <stdint.h>

#define S_LEN 2048
#define DIM 2560
#define N_HEAD 32
#define HEAD_DIM 80
#define ROT_DIM 32
#define INTER 10240
#define EPS 1e-5f

// ---------------- scratch ----------------
__device__ __half g_h   [S_LEN * DIM];
__device__ float  g_qkv [S_LEN * 3 * DIM];
__device__ __half g_y   [S_LEN * DIM];
__device__ float  g_attn[S_LEN * DIM];
__device__ __half g_ffn1[S_LEN * INTER];
__device__ __half g_qh [N_HEAD * S_LEN * HEAD_DIM];
__device__ __half g_kh [N_HEAD * S_LEN * HEAD_DIM];
__device__ __half g_vh [N_HEAD * S_LEN * HEAD_DIM];

// ---------------- helpers ----------------
__device__ __forceinline__ uint32_t smem_u32(const void* p) {
    uint32_t a;
    asm("{ .reg .u64 t; cvta.to.shared.u64 t, %1; cvt.u32.u64 %0, t; }" : "=r"(a) : "l"(p));
    return a;
}
__device__ __forceinline__ uint32_t pkh(__half a, __half b) {
    __half2 t = __halves2half2(a, b);
    return *(uint32_t*)&t;
}
__device__ __forceinline__ uint32_t pkf(float a, float b) {
    return pkh(__float2half_rn(a), __float2half_rn(b));
}
__device__ __forceinline__ void ldsm4(uint32_t r[4], uint32_t addr) {
    asm volatile("ldmatrix.sync.aligned.m8n8.x4.shared.b16 {%0,%1,%2,%3}, [%4];"
                 : "=r"(r[0]), "=r"(r[1]), "=r"(r[2]), "=r"(r[3]) : "r"(addr));
}
__device__ __forceinline__ void ldsm4t(uint32_t r[4], uint32_t addr) {
    asm volatile("ldmatrix.sync.aligned.m8n8.x4.trans.shared.b16 {%0,%1,%2,%3}, [%4];"
                 : "=r"(r[0]), "=r"(r[1]), "=r"(r[2]), "=r"(r[3]) : "r"(addr));
}
__device__ __forceinline__ void mma16816(float c[4], const uint32_t a[4], const uint32_t b[2]) {
    asm volatile("mma.sync.aligned.m16n8k16.row.col.f32.f16.f16.f32 "
                 "{%0,%1,%2,%3}, {%4,%5,%6,%7}, {%8,%9}, {%0,%1,%2,%3};"
                 : "+f"(c[0]), "+f"(c[1]), "+f"(c[2]), "+f"(c[3])
                 : "r"(a[0]), "r"(a[1]), "r"(a[2]), "r"(a[3]), "r"(b[0]), "r"(b[1]));
}
__device__ __forceinline__ float gelu_tanh(float v) {
    float c = v + 0.044715f * v * v * v;
    return 0.5f * v * (1.f + tanhf(0.7978845608028654f * c));
}

#define BK 32
#define LDT 40

// =========== BM=128 GEMM (round-15 winner, unchanged) ===========
#define TILE_H (128 * LDT)
#define TILE_B (TILE_H * 2)
#define BUF_H  (3 * TILE_H)
#define SMEM_DYN 81920

template<int EPI>
__global__ __launch_bounds__(256)
void mma_gemm(const __half* __restrict__ A, const float* __restrict__ W,
              const float* __restrict__ bias,
              float* __restrict__ C, __half* __restrict__ Ch,
              int M, int N, int K,
              const float* __restrict__ res1, const float* __restrict__ res2)
{
    extern __shared__ __align__(16) __half smem[];
    const int tid  = threadIdx.x;
    const int lane = tid & 31;
    const int wid  = tid >> 5;
    const int wm   = (wid & 3) * 32;
    const int wn   = (wid >> 2) * 64;
    const int m0 = blockIdx.x * 128;
    const int n0 = blockIdx.y * 128;

    float acc[2][8][4];
    #pragma unroll
    for (int i = 0; i < 2; i++)
        #pragma unroll
        for (int j = 0; j < 8; j++)
            #pragma unroll
            for (int q = 0; q < 4; q++) acc[i][j][q] = 0.f;

    const int nch = K / BK;
    uint4  ua[2];
    float4 rw[4];

    auto stage = [&](int k0) {
        #pragma unroll
        for (int r = 0; r < 2; r++) {
            const int idx = r * 256 + tid;
            const int rr = idx >> 2, seg = idx & 3;
            ua[r] = *(const uint4*)(A + (size_t)(m0 + rr) * K + k0 + seg * 8);
        }
        #pragma unroll
        for (int r = 0; r < 4; r++) {
            const int idx = r * 256 + tid;
            const int rr = idx >> 3, c4 = idx & 7;
            rw[r] = *(const float4*)(W + (size_t)(n0 + rr) * K + k0 + c4 * 4);
        }
    };
    auto storebuf = [&](int b) {
        __half* buf = smem + b * BUF_H;
        #pragma unroll
        for (int r = 0; r < 2; r++) {
            const int idx = r * 256 + tid;
            const int rr = idx >> 2, seg = idx & 3;
            *(uint4*)(buf + rr * LDT + seg * 8) = ua[r];
        }
        #pragma unroll
        for (int r = 0; r < 4; r++) {
            const int idx = r * 256 + tid;
            const int rr = idx >> 3, c4 = idx & 7;
            const int off = rr * LDT + c4 * 4;
            float4 v = rw[r];
            __half h0 = __float2half_rn(v.x), h1 = __float2half_rn(v.y);
            __half h2 = __float2half_rn(v.z), h3 = __float2half_rn(v.w);
            __half l0 = __float2half_rn(v.x - __half2float(h0));
            __half l1 = __float2half_rn(v.y - __half2float(h1));
            __half l2 = __float2half_rn(v.z - __half2float(h2));
            __half l3 = __float2half_rn(v.w - __half2float(h3));
            *(uint2*)(buf + 1 * TILE_H + off) = make_uint2(pkh(h0, h1), pkh(h2, h3));
            *(uint2*)(buf + 2 * TILE_H + off) = make_uint2(pkh(l0, l1), pkh(l2, l3));
        }
    };

    const int a_row    = wm + (lane & 15);
    const int a_colsel = (lane >> 4) << 3;
    const int b_rowsel = ((lane >> 4) & 1) * 8 + (lane & 7);
    const int b_colsel = ((lane >> 3) & 1) * 8;

    auto compute = [&](int b) {
        const uint32_t base = smem_u32(smem + b * BUF_H);
        #pragma unroll
        for (int ks = 0; ks < 2; ks++) {
            const int kb = ks * 16;
            uint32_t ah[2][4], bh[8][2], bl[8][2];
            #pragma unroll
            for (int i = 0; i < 2; i++) {
                const uint32_t off = ((a_row + i * 16) * LDT + kb + a_colsel) * 2;
                ldsm4(ah[i], base + off);
            }
            #pragma unroll
            for (int p = 0; p < 4; p++) {
                const int nrow = wn + p * 16 + b_rowsel;
                const uint32_t off = (nrow * LDT + kb + b_colsel) * 2;
                uint32_t t[4];
                ldsm4(t, base + 1 * TILE_B + off);
                bh[2 * p][0] = t[0]; bh[2 * p][1] = t[1];
                bh[2 * p + 1][0] = t[2]; bh[2 * p + 1][1] = t[3];
                ldsm4(t, base + 2 * TILE_B + off);
                bl[2 * p][0] = t[0]; bl[2 * p][1] = t[1];
                bl[2 * p + 1][0] = t[2]; bl[2 * p + 1][1] = t[3];
            }
            #pragma unroll
            for (int i = 0; i < 2; i++)
                #pragma unroll
                for (int j = 0; j < 8; j++) mma16816(acc[i][j], ah[i], bh[j]);
            #pragma unroll
            for (int i = 0; i < 2; i++)
                #pragma unroll
                for (int j = 0; j < 8; j++) mma16816(acc[i][j], ah[i], bl[j]);
        }
    };

    stage(0);
    storebuf(0);
    __syncthreads();

    for (int ch = 0; ch < nch; ch++) {
        if (ch + 1 < nch) stage((ch + 1) * BK);
        compute(ch & 1);
        if (ch + 1 < nch) storebuf((ch + 1) & 1);
        __syncthreads();
    }

    #pragma unroll
    for (int i = 0; i < 2; i++) {
        const int row = m0 + wm + i * 16 + (lane >> 2);
        #pragma unroll
        for (int j = 0; j < 8; j++) {
            const int col = n0 + wn + j * 8 + (lane & 3) * 2;
            const float b0 = bias[col], b1 = bias[col + 1];
            #pragma unroll
            for (int half_ = 0; half_ < 2; half_++) {
                const int r = row + half_ * 8;
                float v0 = acc[i][j][half_ * 2 + 0] + b0;
                float v1 = acc[i][j][half_ * 2 + 1] + b1;
                const size_t off = (size_t)r * N + col;
                if (EPI == 1) {
                    v0 = gelu_tanh(v0); v1 = gelu_tanh(v1);
                    *(uint32_t*)(Ch + off) = pkf(v0, v1);
                } else {
                    if (EPI == 2) {
                        float2 r1 = *(const float2*)(res1 + off);
                        float2 r2 = *(const float2*)(res2 + off);
                        v0 += r1.x + r2.x; v1 += r1.y + r2.y;
                    }
                    *(float2*)(C + off) = make_float2(v0, v1);
                }
            }
        }
    }
}

// =========== BM=256 GEMM (warp tile m64 x n64; for big-N GEMMs) ===========
#define BTILE_A_H (256 * LDT)                 // A tile halves
#define BTILE_W_H (128 * LDT)                 // W hi (or lo) tile halves
#define BBUF_H    (BTILE_A_H + 2 * BTILE_W_H) // 20480 halves = 40960 B

template<int EPI>
__global__ __launch_bounds__(256, 1)
void mma_gemm_big(const __half* __restrict__ A, const float* __restrict__ W,
                  const float* __restrict__ bias,
                  float* __restrict__ C, __half* __restrict__ Ch,
                  int M, int N, int K)
{
    extern __shared__ __align__(16) __half smem[];
    const int tid  = threadIdx.x;
    const int lane = tid & 31;
    const int wid  = tid >> 5;
    const int wm   = (wid & 3) * 64;
    const int wn   = (wid >> 2) * 64;
    const int m0 = blockIdx.x * 256;
    const int n0 = blockIdx.y * 128;

    float acc[4][8][4];
    #pragma unroll
    for (int i = 0; i < 4; i++)
        #pragma unroll
        for (int j = 0; j < 8; j++)
            #pragma unroll
            for (int q = 0; q < 4; q++) acc[i][j][q] = 0.f;

    const int nch = K / BK;
    uint4  ua[4];
    float4 rw[4];

    auto stage = [&](int k0) {
        #pragma unroll
        for (int r = 0; r < 4; r++) {
            const int idx = r * 256 + tid;          // 0..1023
            const int rr = idx >> 2, seg = idx & 3;
            ua[r] = *(const uint4*)(A + (size_t)(m0 + rr) * K + k0 + seg * 8);
        }
        #pragma unroll
        for (int r = 0; r < 4; r++) {
            const int idx = r * 256 + tid;
            const int rr = idx >> 3, c4 = idx & 7;
            rw[r] = *(const float4*)(W + (size_t)(n0 + rr) * K + k0 + c4 * 4);
        }
    };
    auto storebuf = [&](int b) {
        __half* buf = smem + b * BBUF_H;
        #pragma unroll
        for (int r = 0; r < 4; r++) {
            const int idx = r * 256 + tid;
            const int rr = idx >> 2, seg = idx & 3;
            *(uint4*)(buf + rr * LDT + seg * 8) = ua[r];
        }
        #pragma unroll
        for (int r = 0; r < 4; r++) {
            const int idx = r * 256 + tid;
            const int rr = idx >> 3, c4 = idx & 7;
            const int off = rr * LDT + c4 * 4;
            float4 v = rw[r];
            __half h0 = __float2half_rn(v.x), h1 = __float2half_rn(v.y);
            __half h2 = __float2half_rn(v.z), h3 = __float2half_rn(v.w);
            __half l0 = __float2half_rn(v.x - __half2float(h0));
            __half l1 = __float2half_rn(v.y - __half2float(h1));
            __half l2 = __float2half_rn(v.z - __half2float(h2));
            __half l3 = __float2half_rn(v.w - __half2float(h3));
            *(uint2*)(buf + BTILE_A_H + off)             = make_uint2(pkh(h0, h1), pkh(h2, h3));
            *(uint2*)(buf + BTILE_A_H + BTILE_W_H + off) = make_uint2(pkh(l0, l1), pkh(l2, l3));
        }
    };

    const int a_row    = wm + (lane & 15);
    const int a_colsel = (lane >> 4) << 3;
    const int b_rowsel = ((lane >> 4) & 1) * 8 + (lane & 7);
    const int b_colsel = ((lane >> 3) & 1) * 8;

    auto compute = [&](int b) {
        const uint32_t base = smem_u32(smem + b * BBUF_H);
        #pragma unroll
        for (int ks = 0; ks < 2; ks++) {
            const int kb = ks * 16;
            uint32_t ah[4][4], bb[8][2];
            #pragma unroll
            for (int i = 0; i < 4; i++) {
                const uint32_t off = ((a_row + i * 16) * LDT + kb + a_colsel) * 2;
                ldsm4(ah[i], base + off);
            }
            // hi pass
            #pragma unroll
            for (int p = 0; p < 4; p++) {
                const int nrow = wn + p * 16 + b_rowsel;
                const uint32_t off = (nrow * LDT + kb + b_colsel) * 2;
                uint32_t t[4];
                ldsm4(t, base + BTILE_A_H * 2 + off);
                bb[2 * p][0] = t[0]; bb[2 * p][1] = t[1];
                bb[2 * p + 1][0] = t[2]; bb[2 * p + 1][1] = t[3];
            }
            #pragma unroll
            for (int i = 0; i < 4; i++)
                #pragma unroll
                for (int j = 0; j < 8; j++) mma16816(acc[i][j], ah[i], bb[j]);
            // lo pass
            #pragma unroll
            for (int p = 0; p < 4; p++) {
                const int nrow = wn + p * 16 + b_rowsel;
                const uint32_t off = (nrow * LDT + kb + b_colsel) * 2;
                uint32_t t[4];
                ldsm4(t, base + (BTILE_A_H + BTILE_W_H) * 2 + off);
                bb[2 * p][0] = t[0]; bb[2 * p][1] = t[1];
                bb[2 * p + 1][0] = t[2]; bb[2 * p + 1][1] = t[3];
            }
            #pragma unroll
            for (int i = 0; i < 4; i++)
                #pragma unroll
                for (int j = 0; j < 8; j++) mma16816(acc[i][j], ah[i], bb[j]);
        }
    };

    stage(0);
    storebuf(0);
    __syncthreads();

    for (int ch = 0; ch < nch; ch++) {
        if (ch + 1 < nch) stage((ch + 1) * BK);
        compute(ch & 1);
        if (ch + 1 < nch) storebuf((ch + 1) & 1);
        __syncthreads();
    }

    #pragma unroll
    for (int i = 0; i < 4; i++) {
        const int row = m0 + wm + i * 16 + (lane >> 2);
        #pragma unroll
        for (int j = 0; j < 8; j++) {
            const int col = n0 + wn + j * 8 + (lane & 3) * 2;
            const float b0 = bias[col], b1 = bias[col + 1];
            #pragma unroll
            for (int half_ = 0; half_ < 2; half_++) {
                const int r = row + half_ * 8;
                float v0 = acc[i][j][half_ * 2 + 0] + b0;
                float v1 = acc[i][j][half_ * 2 + 1] + b1;
                const size_t off = (size_t)r * N + col;
                if (EPI == 1) {
                    v0 = gelu_tanh(v0); v1 = gelu_tanh(v1);
                    *(uint32_t*)(Ch + off) = pkf(v0, v1);
                } else {
                    *(float2*)(C + off) = make_float2(v0, v1);
                }
            }
        }
    }
}

// ---------------- LayerNorm -> fp16 ----------------
__global__ void ln_kernel(const float* __restrict__ x,
                          const float* __restrict__ w,
                          const float* __restrict__ b)
{
    const int s = blockIdx.x;
    const int tid = threadIdx.x;
    const float* row = x + (size_t)s * DIM;
    float sum = 0.f, sumsq = 0.f;
    for (int i = tid; i < DIM; i += 256) {
        float v = row[i];
        sum += v; sumsq += v * v;
    }
    __shared__ float r1[256], r2[256];
    r1[tid] = sum; r2[tid] = sumsq;
    __syncthreads();
    for (int st = 128; st > 0; st >>= 1) {
        if (tid < st) { r1[tid] += r1[tid + st]; r2[tid] += r2[tid + st]; }
        __syncthreads();
    }
    const float mu  = r1[0] * (1.f / DIM);
    const float var = r2[0] * (1.f / DIM) - mu * mu;
    const float rstd = rsqrtf(var + EPS);
    for (int i = tid; i < DIM; i += 256)
        g_h[(size_t)s * DIM + i] = __float2half_rn((row[i] - mu) * rstd * w[i] + b[i]);
}

// ---------------- split QKV + RoPE -> fp16 head-major ----------------
__global__ void prep_qkv_kernel(const float* __restrict__ qkv,
                                const int* __restrict__ input_pos)
{
    const int s = blockIdx.x;
    const float pos = (float)input_pos[s];
    const float* row = qkv + (size_t)s * (3 * DIM);
    for (int idx = threadIdx.x; idx < DIM; idx += 256) {
        const int h = idx / HEAD_DIM;
        const int d = idx - h * HEAD_DIM;
        const size_t dsti = ((size_t)h * S_LEN + s) * HEAD_DIM + d;

        float qv = row[idx];
        float kv = row[DIM + idx];
        float vv = row[2 * DIM + idx];

        if (d < ROT_DIM) {
            const int i = (d < 16) ? d : d - 16;
            const float inv = __powf(10000.f, -(float)i / 16.f);
            const float ang = pos * inv;
            const float c = __cosf(ang), sn = __sinf(ang);
            if (d < 16) {
                float q2 = row[idx + 16];
                float k2 = row[DIM + idx + 16];
                qv = qv * c - q2 * sn;
                kv = kv * c - k2 * sn;
            } else {
                float q2 = row[idx - 16];
                float k2 = row[DIM + idx - 16];
                qv = qv * c + q2 * sn;
                kv = kv * c + k2 * sn;
            }
        }
        g_qh[dsti] = __float2half_rn(qv);
        g_kh[dsti] = __float2half_rn(kv);
        g_vh[dsti] = __float2half_rn(vv);
    }
}

// ---------------- tensor-core flash attention ----------------
#define LDQ 88

__global__ __launch_bounds__(128)
void attn_kernel(__half* __restrict__ y)
{
    __shared__ __half sq[64 * LDQ];
    __shared__ __half sk[64 * LDQ];
    __shared__ __half sv[64 * LDQ];

    const int tid  = threadIdx.x;
    const int lane = tid & 31;
    const int warp = tid >> 5;
    const int qb = blockIdx.x;
    const int h  = blockIdx.y;
    const uint32_t sqb = smem_u32(sq);
    const uint32_t skb = smem_u32(sk);
    const uint32_t svb = smem_u32(sv);
    const float scale = 0.11180339887498949f;

    {
        const __half* qg = g_qh + ((size_t)h * S_LEN + qb * 64) * HEAD_DIM;
        #pragma unroll
        for (int p = 0; p < 5; p++) {
            const int idx = p * 128 + tid;
            const int r = idx / 10, seg = idx % 10;
            *(uint4*)(sq + r * LDQ + seg * 8) = *(const uint4*)(qg + r * 80 + seg * 8);
        }
    }
    __syncthreads();

    uint32_t qa[5][4];
    {
        const uint32_t a_off = (uint32_t)((warp * 16 + (lane & 15)) * LDQ + ((lane >> 4) << 3)) * 2;
        #pragma unroll
        for (int ks = 0; ks < 5; ks++) ldsm4(qa[ks], sqb + a_off + ks * 32);
    }

    float o[10][4];
    #pragma unroll
    for (int j = 0; j < 10; j++)
        #pragma unroll
        for (int e = 0; e < 4; e++) o[j][e] = 0.f;
    float mr0 = -1e30f, mr1 = -1e30f, lr0 = 0.f, lr1 = 0.f;

    const int row0 = qb * 64 + warp * 16 + (lane >> 2);
    const uint32_t b_off = (uint32_t)(((((lane >> 4) & 1) * 8 + (lane & 7)) * LDQ) + ((lane >> 3) & 1) * 8) * 2;
    const uint32_t v_off = (uint32_t)((lane & 15) * LDQ + ((lane >> 4) << 3)) * 2;

    for (int kb = 0; kb <= qb; kb++) {
        {
            const __half* kg = g_kh + ((size_t)h * S_LEN + kb * 64) * HEAD_DIM;
            const __half* vg = g_vh + ((size_t)h * S_LEN + kb * 64) * HEAD_DIM;
            #pragma unroll
            for (int p = 0; p < 5; p++) {
                const int idx = p * 128 + tid;
                const int r = idx / 10, seg = idx % 10;
                *(uint4*)(sk + r * LDQ + seg * 8) = *(const uint4*)(kg + r * 80 + seg * 8);
                *(uint4*)(sv + r * LDQ + seg * 8) = *(const uint4*)(vg + r * 80 + seg * 8);
            }
        }
        __syncthreads();

        float s[8][4];
        #pragma unroll
        for (int j = 0; j < 8; j++)
            #pragma unroll
            for (int e = 0; e < 4; e++) s[j][e] = 0.f;
        #pragma unroll
        for (int ks = 0; ks < 5; ks++) {
            #pragma unroll
            for (int p = 0; p < 4; p++) {
                uint32_t t[4];
                ldsm4(t, skb + b_off + (uint32_t)(p * 16 * LDQ) * 2 + ks * 32);
                mma16816(s[2 * p],     qa[ks], t);
                mma16816(s[2 * p + 1], qa[ks], t + 2);
            }
        }

        if (kb == qb) {
            #pragma unroll
            for (int j = 0; j < 8; j++)
                #pragma unroll
                for (int e = 0; e < 4; e++) {
                    const int col = kb * 64 + j * 8 + (lane & 3) * 2 + (e & 1);
                    const int row = row0 + (e >> 1) * 8;
                    s[j][e] = (col <= row) ? s[j][e] * scale : -1e30f;
                }
        } else {
            #pragma unroll
            for (int j = 0; j < 8; j++)
                #pragma unroll
                for (int e = 0; e < 4; e++) s[j][e] *= scale;
        }

        float m0 = -1e30f, m1 = -1e30f;
        #pragma unroll
        for (int j = 0; j < 8; j++) {
            m0 = fmaxf(m0, fmaxf(s[j][0], s[j][1]));
            m1 = fmaxf(m1, fmaxf(s[j][2], s[j][3]));
        }
        m0 = fmaxf(m0, __shfl_xor_sync(0xffffffffu, m0, 1));
        m0 = fmaxf(m0, __shfl_xor_sync(0xffffffffu, m0, 2));
        m1 = fmaxf(m1, __shfl_xor_sync(0xffffffffu, m1, 1));
        m1 = fmaxf(m1, __shfl_xor_sync(0xffffffffu, m1, 2));

        const float mn0 = fmaxf(mr0, m0), mn1 = fmaxf(mr1, m1);
        const float al0 = __expf(mr0 - mn0), al1 = __expf(mr1 - mn1);

        float lp0 = 0.f, lp1 = 0.f;
        #pragma unroll
        for (int j = 0; j < 8; j++) {
            s[j][0] = __expf(s[j][0] - mn0); lp0 += s[j][0];
            s[j][1] = __expf(s[j][1] - mn0); lp0 += s[j][1];
            s[j][2] = __expf(s[j][2] - mn1); lp1 += s[j][2];
            s[j][3] = __expf(s[j][3] - mn1); lp1 += s[j][3];
        }
        lp0 += __shfl_xor_sync(0xffffffffu, lp0, 1);
        lp0 += __shfl_xor_sync(0xffffffffu, lp0, 2);
        lp1 += __shfl_xor_sync(0xffffffffu, lp1, 1);
        lp1 += __shfl_xor_sync(0xffffffffu, lp1, 2);

        lr0 = lr0 * al0 + lp0;
        lr1 = lr1 * al1 + lp1;
        mr0 = mn0; mr1 = mn1;

        #pragma unroll
        for (int j = 0; j < 10; j++) {
            o[j][0] *= al0; o[j][1] *= al0;
            o[j][2] *= al1; o[j][3] *= al1;
        }

        uint32_t pa[4][4];
        #pragma unroll
        for (int ks2 = 0; ks2 < 4; ks2++) {
            pa[ks2][0] = pkf(s[2 * ks2][0],     s[2 * ks2][1]);
            pa[ks2][1] = pkf(s[2 * ks2][2],     s[2 * ks2][3]);
            pa[ks2][2] = pkf(s[2 * ks2 + 1][0], s[2 * ks2 + 1][1]);
            pa[ks2][3] = pkf(s[2 * ks2 + 1][2], s[2 * ks2 + 1][3]);
        }

        #pragma unroll
        for (int ks2 = 0; ks2 < 4; ks2++) {
            #pragma unroll
            for (int np = 0; np < 5; np++) {
                uint32_t t[4];
                ldsm4t(t, svb + v_off + (uint32_t)(ks2 * 16 * LDQ) * 2 + np * 32);
                mma16816(o[2 * np],     pa[ks2], t);
                mma16816(o[2 * np + 1], pa[ks2], t + 2);
            }
        }

        __syncthreads();
    }

    const float il0 = 1.f / lr0, il1 = 1.f / lr1;
    #pragma unroll
    for (int j = 0; j < 10; j++) {
        const int col = h * HEAD_DIM + j * 8 + (lane & 3) * 2;
        *(uint32_t*)(y + (size_t)row0 * DIM + col)       = pkf(o[j][0] * il0, o[j][1] * il0);
        *(uint32_t*)(y + (size_t)(row0 + 8) * DIM + col) = pkf(o[j][2] * il1, o[j][3] * il1);
    }
}

// ---------------- host launch ----------------
extern "C" void kernel_launch(void* const* d_in, const int* in_sizes, int n_in,
                              void* d_out, int out_size)
{
    const float* x       = (const float*)d_in[0];
    const int*   pos     = (const int*)  d_in[1];
    const float* ln_w    = (const float*)d_in[3];
    const float* ln_b    = (const float*)d_in[4];
    const float* wqkv_w  = (const float*)d_in[5];
    const float* wqkv_b  = (const float*)d_in[6];
    const float* wo_w    = (const float*)d_in[7];
    const float* wo_b    = (const float*)d_in[8];
    const float* w1_w    = (const float*)d_in[9];
    const float* w1_b    = (const float*)d_in[10];
    const float* w2_w    = (const float*)d_in[11];
    const float* w2_b    = (const float*)d_in[12];
    float* out = (float*)d_out;

    float *qkv_p, *attn_p;
    __half *h_p, *y_p, *ffn1_p;
    cudaGetSymbolAddress((void**)&h_p,    g_h);
    cudaGetSymbolAddress((void**)&qkv_p,  g_qkv);
    cudaGetSymbolAddress((void**)&y_p,    g_y);
    cudaGetSymbolAddress((void**)&attn_p, g_attn);
    cudaGetSymbolAddress((void**)&ffn1_p, g_ffn1);

    cudaFuncSetAttribute(mma_gemm<0>, cudaFuncAttributeMaxDynamicSharedMemorySize, SMEM_DYN);
    cudaFuncSetAttribute(mma_gemm<2>, cudaFuncAttributeMaxDynamicSharedMemorySize, SMEM_DYN);
    cudaFuncSetAttribute(mma_gemm_big<0>, cudaFuncAttributeMaxDynamicSharedMemorySize, SMEM_DYN);
    cudaFuncSetAttribute(mma_gemm_big<1>, cudaFuncAttributeMaxDynamicSharedMemorySize, SMEM_DYN);

    // 1. LayerNorm -> fp16 h
    ln_kernel<<<S_LEN, 256>>>(x, ln_w, ln_b);

    // 2. QKV projection (BM=256)
    mma_gemm_big<0><<<dim3(S_LEN / 256, 3 * DIM / 128), 256, SMEM_DYN>>>(
        h_p, wqkv_w, wqkv_b, qkv_p, nullptr, S_LEN, 3 * DIM, DIM);

    // 3. split + RoPE -> fp16
    prep_qkv_kernel<<<S_LEN, 256>>>(qkv_p, pos);

    // 4. tensor-core flash attention -> fp16 y
    attn_kernel<<<dim3(S_LEN / 64, N_HEAD), 128>>>(y_p);

    // 5. output projection (BM=128; avoids wave tail at N=2560)
    mma_gemm<0><<<dim3(S_LEN / 128, DIM / 128), 256, SMEM_DYN>>>(
        y_p, wo_w, wo_b, attn_p, nullptr, S_LEN, DIM, DIM, nullptr, nullptr);

    // 6. FFN up + gelu (BM=256) -> fp16 ffn1
    mma_gemm_big<1><<<dim3(S_LEN / 256, INTER / 128), 256, SMEM_DYN>>>(
        h_p, w1_w, w1_b, nullptr, ffn1_p, S_LEN, INTER, DIM);

    // 7. FFN down + residual fuse (BM=128)
    mma_gemm<2><<<dim3(S_LEN / 128, DIM / 128), 256, SMEM_DYN>>>(
        ffn1_p, w2_w, w2_b, out, nullptr, S_LEN, DIM, INTER, attn_p, x);
}

// round 17
// speedup vs baseline: 1.0076x; 1.0076x over previous
#include <cuda_runtime.h>
#include <cuda_fp16.h>
#include <math.h>
#include <stdint.h>

#define S_LEN 2048
#define DIM 2560
#define N_HEAD 32
#define HEAD_DIM 80
#define ROT_DIM 32
#define INTER 10240
#define EPS 1e-5f

// ---------------- scratch ----------------
__device__ __half g_h   [S_LEN * DIM];
__device__ float  g_qkv [S_LEN * 3 * DIM];
__device__ __half g_y   [S_LEN * DIM];
__device__ float  g_attn[S_LEN * DIM];
__device__ __half g_ffn1[S_LEN * INTER];
__device__ __half g_qh [N_HEAD * S_LEN * HEAD_DIM];
__device__ __half g_kh [N_HEAD * S_LEN * HEAD_DIM];
__device__ __half g_vh [N_HEAD * S_LEN * HEAD_DIM];
// weight hi/lo splits
__device__ __half s_wqkv_h[3 * DIM * DIM], s_wqkv_l[3 * DIM * DIM];
__device__ __half s_wo_h  [DIM * DIM],     s_wo_l  [DIM * DIM];
__device__ __half s_w1_h  [INTER * DIM],   s_w1_l  [INTER * DIM];
__device__ __half s_w2_h  [DIM * INTER],   s_w2_l  [DIM * INTER];

// ---------------- helpers ----------------
__device__ __forceinline__ uint32_t smem_u32(const void* p) {
    uint32_t a;
    asm("{ .reg .u64 t; cvta.to.shared.u64 t, %1; cvt.u32.u64 %0, t; }" : "=r"(a) : "l"(p));
    return a;
}
__device__ __forceinline__ uint32_t pkh(__half a, __half b) {
    __half2 t = __halves2half2(a, b);
    return *(uint32_t*)&t;
}
__device__ __forceinline__ uint32_t pkf(float a, float b) {
    return pkh(__float2half_rn(a), __float2half_rn(b));
}
__device__ __forceinline__ void ldsm4(uint32_t r[4], uint32_t addr) {
    asm volatile("ldmatrix.sync.aligned.m8n8.x4.shared.b16 {%0,%1,%2,%3}, [%4];"
                 : "=r"(r[0]), "=r"(r[1]), "=r"(r[2]), "=r"(r[3]) : "r"(addr));
}
__device__ __forceinline__ void ldsm4t(uint32_t r[4], uint32_t addr) {
    asm volatile("ldmatrix.sync.aligned.m8n8.x4.trans.shared.b16 {%0,%1,%2,%3}, [%4];"
                 : "=r"(r[0]), "=r"(r[1]), "=r"(r[2]), "=r"(r[3]) : "r"(addr));
}
__device__ __forceinline__ void mma16816(float c[4], const uint32_t a[4], const uint32_t b[2]) {
    asm volatile("mma.sync.aligned.m16n8k16.row.col.f32.f16.f16.f32 "
                 "{%0,%1,%2,%3}, {%4,%5,%6,%7}, {%8,%9}, {%0,%1,%2,%3};"
                 : "+f"(c[0]), "+f"(c[1]), "+f"(c[2]), "+f"(c[3])
                 : "r"(a[0]), "r"(a[1]), "r"(a[2]), "r"(a[3]), "r"(b[0]), "r"(b[1]));
}
__device__ __forceinline__ float gelu_tanh(float v) {
    float c = v + 0.044715f * v * v * v;
    return 0.5f * v * (1.f + tanhf(0.7978845608028654f * c));
}

// ---------------- fp32 -> fp16 hi/lo weight split ----------------
__global__ __launch_bounds__(256)
void split_kernel(const float* __restrict__ src, __half* __restrict__ dh,
                  __half* __restrict__ dl, int n4)
{
    const int stride = gridDim.x * 256;
    for (int i = blockIdx.x * 256 + threadIdx.x; i < n4; i += stride) {
        float4 v = *(const float4*)(src + (size_t)i * 4);
        __half h0 = __float2half_rn(v.x), h1 = __float2half_rn(v.y);
        __half h2 = __float2half_rn(v.z), h3 = __float2half_rn(v.w);
        __half l0 = __float2half_rn(v.x - __half2float(h0));
        __half l1 = __float2half_rn(v.y - __half2float(h1));
        __half l2 = __float2half_rn(v.z - __half2float(h2));
        __half l3 = __float2half_rn(v.w - __half2float(h3));
        *(uint2*)(dh + (size_t)i * 4) = make_uint2(pkh(h0, h1), pkh(h2, h3));
        *(uint2*)(dl + (size_t)i * 4) = make_uint2(pkh(l0, l1), pkh(l2, l3));
    }
}

// ---------------- mma.sync fp16x2 GEMM: C = A(fp16) @ (Wh+Wl)^T + bias ----------------
// Round-15 skeleton; staging is now pure uint4 copies (no in-loop conversion).
#define BK 32
#define LDT 40
#define TILE_H (128 * LDT)
#define TILE_B (TILE_H * 2)
#define BUF_H  (3 * TILE_H)
#define SMEM_DYN 81920

// EPI: 0 -> fp32 C; 1 -> gelu -> fp16 Ch; 2 -> fp32 C + res1 + res2
template<int EPI>
__global__ __launch_bounds__(256)
void mma_gemm(const __half* __restrict__ A,
              const __half* __restrict__ Wh_, const __half* __restrict__ Wl_,
              const float* __restrict__ bias,
              float* __restrict__ C, __half* __restrict__ Ch,
              int M, int N, int K,
              const float* __restrict__ res1, const float* __restrict__ res2)
{
    extern __shared__ __align__(16) __half smem[];
    const int tid  = threadIdx.x;
    const int lane = tid & 31;
    const int wid  = tid >> 5;
    const int wm   = (wid & 3) * 32;
    const int wn   = (wid >> 2) * 64;
    const int m0 = blockIdx.x * 128;
    const int n0 = blockIdx.y * 128;

    float acc[2][8][4];
    #pragma unroll
    for (int i = 0; i < 2; i++)
        #pragma unroll
        for (int j = 0; j < 8; j++)
            #pragma unroll
            for (int q = 0; q < 4; q++) acc[i][j][q] = 0.f;

    const int nch = K / BK;
    uint4 ua[2], uh[2], ul[2];

    // mapping for 128x32-half tiles: idx = rep*256+tid; row = idx>>2; seg = idx&3
    auto stage = [&](int k0) {
        #pragma unroll
        for (int r = 0; r < 2; r++) {
            const int idx = r * 256 + tid;
            const int rr = idx >> 2, seg = idx & 3;
            const size_t aoff = (size_t)(m0 + rr) * K + k0 + seg * 8;
            const size_t woff = (size_t)(n0 + rr) * K + k0 + seg * 8;
            ua[r] = *(const uint4*)(A + aoff);
            uh[r] = *(const uint4*)(Wh_ + woff);
            ul[r] = *(const uint4*)(Wl_ + woff);
        }
    };
    auto storebuf = [&](int b) {
        __half* buf = smem + b * BUF_H;
        #pragma unroll
        for (int r = 0; r < 2; r++) {
            const int idx = r * 256 + tid;
            const int rr = idx >> 2, seg = idx & 3;
            const int off = rr * LDT + seg * 8;
            *(uint4*)(buf + off)              = ua[r];
            *(uint4*)(buf + 1 * TILE_H + off) = uh[r];
            *(uint4*)(buf + 2 * TILE_H + off) = ul[r];
        }
    };

    const int a_row    = wm + (lane & 15);
    const int a_colsel = (lane >> 4) << 3;
    const int b_rowsel = ((lane >> 4) & 1) * 8 + (lane & 7);
    const int b_colsel = ((lane >> 3) & 1) * 8;

    auto compute = [&](int b) {
        const uint32_t base = smem_u32(smem + b * BUF_H);
        #pragma unroll
        for (int ks = 0; ks < 2; ks++) {
            const int kb = ks * 16;
            uint32_t ah[2][4], bh[8][2], bl[8][2];
            #pragma unroll
            for (int i = 0; i < 2; i++) {
                const uint32_t off = ((a_row + i * 16) * LDT + kb + a_colsel) * 2;
                ldsm4(ah[i], base + off);
            }
            #pragma unroll
            for (int p = 0; p < 4; p++) {
                const int nrow = wn + p * 16 + b_rowsel;
                const uint32_t off = (nrow * LDT + kb + b_colsel) * 2;
                uint32_t t[4];
                ldsm4(t, base + 1 * TILE_B + off);
                bh[2 * p][0] = t[0]; bh[2 * p][1] = t[1];
                bh[2 * p + 1][0] = t[2]; bh[2 * p + 1][1] = t[3];
                ldsm4(t, base + 2 * TILE_B + off);
                bl[2 * p][0] = t[0]; bl[2 * p][1] = t[1];
                bl[2 * p + 1][0] = t[2]; bl[2 * p + 1][1] = t[3];
            }
            #pragma unroll
            for (int i = 0; i < 2; i++)
                #pragma unroll
                for (int j = 0; j < 8; j++) mma16816(acc[i][j], ah[i], bh[j]);
            #pragma unroll
            for (int i = 0; i < 2; i++)
                #pragma unroll
                for (int j = 0; j < 8; j++) mma16816(acc[i][j], ah[i], bl[j]);
        }
    };

    stage(0);
    storebuf(0);
    __syncthreads();

    for (int ch = 0; ch < nch; ch++) {
        if (ch + 1 < nch) stage((ch + 1) * BK);
        compute(ch & 1);
        if (ch + 1 < nch) storebuf((ch + 1) & 1);
        __syncthreads();
    }

    #pragma unroll
    for (int i = 0; i < 2; i++) {
        const int row = m0 + wm + i * 16 + (lane >> 2);
        #pragma unroll
        for (int j = 0; j < 8; j++) {
            const int col = n0 + wn + j * 8 + (lane & 3) * 2;
            const float b0 = bias[col], b1 = bias[col + 1];
            #pragma unroll
            for (int half_ = 0; half_ < 2; half_++) {
                const int r = row + half_ * 8;
                float v0 = acc[i][j][half_ * 2 + 0] + b0;
                float v1 = acc[i][j][half_ * 2 + 1] + b1;
                const size_t off = (size_t)r * N + col;
                if (EPI == 1) {
                    v0 = gelu_tanh(v0); v1 = gelu_tanh(v1);
                    *(uint32_t*)(Ch + off) = pkf(v0, v1);
                } else {
                    if (EPI == 2) {
                        float2 r1 = *(const float2*)(res1 + off);
                        float2 r2 = *(const float2*)(res2 + off);
                        v0 += r1.x + r2.x; v1 += r1.y + r2.y;
                    }
                    *(float2*)(C + off) = make_float2(v0, v1);
                }
            }
        }
    }
}

// ---------------- LayerNorm -> fp16 ----------------
__global__ void ln_kernel(const float* __restrict__ x,
                          const float* __restrict__ w,
                          const float* __restrict__ b)
{
    const int s = blockIdx.x;
    const int tid = threadIdx.x;
    const float* row = x + (size_t)s * DIM;
    float sum = 0.f, sumsq = 0.f;
    for (int i = tid; i < DIM; i += 256) {
        float v = row[i];
        sum += v; sumsq += v * v;
    }
    __shared__ float r1[256], r2[256];
    r1[tid] = sum; r2[tid] = sumsq;
    __syncthreads();
    for (int st = 128; st > 0; st >>= 1) {
        if (tid < st) { r1[tid] += r1[tid + st]; r2[tid] += r2[tid + st]; }
        __syncthreads();
    }
    const float mu  = r1[0] * (1.f / DIM);
    const float var = r2[0] * (1.f / DIM) - mu * mu;
    const float rstd = rsqrtf(var + EPS);
    for (int i = tid; i < DIM; i += 256)
        g_h[(size_t)s * DIM + i] = __float2half_rn((row[i] - mu) * rstd * w[i] + b[i]);
}

// ---------------- split QKV + RoPE -> fp16 head-major ----------------
__global__ void prep_qkv_kernel(const float* __restrict__ qkv,
                                const int* __restrict__ input_pos)
{
    const int s = blockIdx.x;
    const float pos = (float)input_pos[s];
    const float* row = qkv + (size_t)s * (3 * DIM);
    for (int idx = threadIdx.x; idx < DIM; idx += 256) {
        const int h = idx / HEAD_DIM;
        const int d = idx - h * HEAD_DIM;
        const size_t dsti = ((size_t)h * S_LEN + s) * HEAD_DIM + d;

        float qv = row[idx];
        float kv = row[DIM + idx];
        float vv = row[2 * DIM + idx];

        if (d < ROT_DIM) {
            const int i = (d < 16) ? d : d - 16;
            const float inv = __powf(10000.f, -(float)i / 16.f);
            const float ang = pos * inv;
            const float c = __cosf(ang), sn = __sinf(ang);
            if (d < 16) {
                float q2 = row[idx + 16];
                float k2 = row[DIM + idx + 16];
                qv = qv * c - q2 * sn;
                kv = kv * c - k2 * sn;
            } else {
                float q2 = row[idx - 16];
                float k2 = row[DIM + idx - 16];
                qv = qv * c + q2 * sn;
                kv = kv * c + k2 * sn;
            }
        }
        g_qh[dsti] = __float2half_rn(qv);
        g_kh[dsti] = __float2half_rn(kv);
        g_vh[dsti] = __float2half_rn(vv);
    }
}

// ---------------- tensor-core flash attention ----------------
#define LDQ 88

__global__ __launch_bounds__(128)
void attn_kernel(__half* __restrict__ y)
{
    __shared__ __half sq[64 * LDQ];
    __shared__ __half sk[64 * LDQ];
    __shared__ __half sv[64 * LDQ];

    const int tid  = threadIdx.x;
    const int lane = tid & 31;
    const int warp = tid >> 5;
    const int qb = blockIdx.x;
    const int h  = blockIdx.y;
    const uint32_t sqb = smem_u32(sq);
    const uint32_t skb = smem_u32(sk);
    const uint32_t svb = smem_u32(sv);
    const float scale = 0.11180339887498949f;

    {
        const __half* qg = g_qh + ((size_t)h * S_LEN + qb * 64) * HEAD_DIM;
        #pragma unroll
        for (int p = 0; p < 5; p++) {
            const int idx = p * 128 + tid;
            const int r = idx / 10, seg = idx % 10;
            *(uint4*)(sq + r * LDQ + seg * 8) = *(const uint4*)(qg + r * 80 + seg * 8);
        }
    }
    __syncthreads();

    uint32_t qa[5][4];
    {
        const uint32_t a_off = (uint32_t)((warp * 16 + (lane & 15)) * LDQ + ((lane >> 4) << 3)) * 2;
        #pragma unroll
        for (int ks = 0; ks < 5; ks++) ldsm4(qa[ks], sqb + a_off + ks * 32);
    }

    float o[10][4];
    #pragma unroll
    for (int j = 0; j < 10; j++)
        #pragma unroll
        for (int e = 0; e < 4; e++) o[j][e] = 0.f;
    float mr0 = -1e30f, mr1 = -1e30f, lr0 = 0.f, lr1 = 0.f;

    const int row0 = qb * 64 + warp * 16 + (lane >> 2);
    const uint32_t b_off = (uint32_t)(((((lane >> 4) & 1) * 8 + (lane & 7)) * LDQ) + ((lane >> 3) & 1) * 8) * 2;
    const uint32_t v_off = (uint32_t)((lane & 15) * LDQ + ((lane >> 4) << 3)) * 2;

    for (int kb = 0; kb <= qb; kb++) {
        {
            const __half* kg = g_kh + ((size_t)h * S_LEN + kb * 64) * HEAD_DIM;
            const __half* vg = g_vh + ((size_t)h * S_LEN + kb * 64) * HEAD_DIM;
            #pragma unroll
            for (int p = 0; p < 5; p++) {
                const int idx = p * 128 + tid;
                const int r = idx / 10, seg = idx % 10;
                *(uint4*)(sk + r * LDQ + seg * 8) = *(const uint4*)(kg + r * 80 + seg * 8);
                *(uint4*)(sv + r * LDQ + seg * 8) = *(const uint4*)(vg + r * 80 + seg * 8);
            }
        }
        __syncthreads();

        float s[8][4];
        #pragma unroll
        for (int j = 0; j < 8; j++)
            #pragma unroll
            for (int e = 0; e < 4; e++) s[j][e] = 0.f;
        #pragma unroll
        for (int ks = 0; ks < 5; ks++) {
            #pragma unroll
            for (int p = 0; p < 4; p++) {
                uint32_t t[4];
                ldsm4(t, skb + b_off + (uint32_t)(p * 16 * LDQ) * 2 + ks * 32);
                mma16816(s[2 * p],     qa[ks], t);
                mma16816(s[2 * p + 1], qa[ks], t + 2);
            }
        }

        if (kb == qb) {
            #pragma unroll
            for (int j = 0; j < 8; j++)
                #pragma unroll
                for (int e = 0; e < 4; e++) {
                    const int col = kb * 64 + j * 8 + (lane & 3) * 2 + (e & 1);
                    const int row = row0 + (e >> 1) * 8;
                    s[j][e] = (col <= row) ? s[j][e] * scale : -1e30f;
                }
        } else {
            #pragma unroll
            for (int j = 0; j < 8; j++)
                #pragma unroll
                for (int e = 0; e < 4; e++) s[j][e] *= scale;
        }

        float m0 = -1e30f, m1 = -1e30f;
        #pragma unroll
        for (int j = 0; j < 8; j++) {
            m0 = fmaxf(m0, fmaxf(s[j][0], s[j][1]));
            m1 = fmaxf(m1, fmaxf(s[j][2], s[j][3]));
        }
        m0 = fmaxf(m0, __shfl_xor_sync(0xffffffffu, m0, 1));
        m0 = fmaxf(m0, __shfl_xor_sync(0xffffffffu, m0, 2));
        m1 = fmaxf(m1, __shfl_xor_sync(0xffffffffu, m1, 1));
        m1 = fmaxf(m1, __shfl_xor_sync(0xffffffffu, m1, 2));

        const float mn0 = fmaxf(mr0, m0), mn1 = fmaxf(mr1, m1);
        const float al0 = __expf(mr0 - mn0), al1 = __expf(mr1 - mn1);

        float lp0 = 0.f, lp1 = 0.f;
        #pragma unroll
        for (int j = 0; j < 8; j++) {
            s[j][0] = __expf(s[j][0] - mn0); lp0 += s[j][0];
            s[j][1] = __expf(s[j][1] - mn0); lp0 += s[j][1];
            s[j][2] = __expf(s[j][2] - mn1); lp1 += s[j][2];
            s[j][3] = __expf(s[j][3] - mn1); lp1 += s[j][3];
        }
        lp0 += __shfl_xor_sync(0xffffffffu, lp0, 1);
        lp0 += __shfl_xor_sync(0xffffffffu, lp0, 2);
        lp1 += __shfl_xor_sync(0xffffffffu, lp1, 1);
        lp1 += __shfl_xor_sync(0xffffffffu, lp1, 2);

        lr0 = lr0 * al0 + lp0;
        lr1 = lr1 * al1 + lp1;
        mr0 = mn0; mr1 = mn1;

        #pragma unroll
        for (int j = 0; j < 10; j++) {
            o[j][0] *= al0; o[j][1] *= al0;
            o[j][2] *= al1; o[j][3] *= al1;
        }

        uint32_t pa[4][4];
        #pragma unroll
        for (int ks2 = 0; ks2 < 4; ks2++) {
            pa[ks2][0] = pkf(s[2 * ks2][0],     s[2 * ks2][1]);
            pa[ks2][1] = pkf(s[2 * ks2][2],     s[2 * ks2][3]);
            pa[ks2][2] = pkf(s[2 * ks2 + 1][0], s[2 * ks2 + 1][1]);
            pa[ks2][3] = pkf(s[2 * ks2 + 1][2], s[2 * ks2 + 1][3]);
        }

        #pragma unroll
        for (int ks2 = 0; ks2 < 4; ks2++) {
            #pragma unroll
            for (int np = 0; np < 5; np++) {
                uint32_t t[4];
                ldsm4t(t, svb + v_off + (uint32_t)(ks2 * 16 * LDQ) * 2 + np * 32);
                mma16816(o[2 * np],     pa[ks2], t);
                mma16816(o[2 * np + 1], pa[ks2], t + 2);
            }
        }

        __syncthreads();
    }

    const float il0 = 1.f / lr0, il1 = 1.f / lr1;
    #pragma unroll
    for (int j = 0; j < 10; j++) {
        const int col = h * HEAD_DIM + j * 8 + (lane & 3) * 2;
        *(uint32_t*)(y + (size_t)row0 * DIM + col)       = pkf(o[j][0] * il0, o[j][1] * il0);
        *(uint32_t*)(y + (size_t)(row0 + 8) * DIM + col) = pkf(o[j][2] * il1, o[j][3] * il1);
    }
}

// ---------------- host launch ----------------
extern "C" void kernel_launch(void* const* d_in, const int* in_sizes, int n_in,
                              void* d_out, int out_size)
{
    const float* x       = (const float*)d_in[0];
    const int*   pos     = (const int*)  d_in[1];
    const float* ln_w    = (const float*)d_in[3];
    const float* ln_b    = (const float*)d_in[4];
    const float* wqkv_w  = (const float*)d_in[5];
    const float* wqkv_b  = (const float*)d_in[6];
    const float* wo_w    = (const float*)d_in[7];
    const float* wo_b    = (const float*)d_in[8];
    const float* w1_w    = (const float*)d_in[9];
    const float* w1_b    = (const float*)d_in[10];
    const float* w2_w    = (const float*)d_in[11];
    const float* w2_b    = (const float*)d_in[12];
    float* out = (float*)d_out;

    float *qkv_p, *attn_p;
    __half *h_p, *y_p, *ffn1_p;
    __half *wqkv_h, *wqkv_l, *wo_h, *wo_l, *w1_h, *w1_l, *w2_h, *w2_l;
    cudaGetSymbolAddress((void**)&h_p,    g_h);
    cudaGetSymbolAddress((void**)&qkv_p,  g_qkv);
    cudaGetSymbolAddress((void**)&y_p,    g_y);
    cudaGetSymbolAddress((void**)&attn_p, g_attn);
    cudaGetSymbolAddress((void**)&ffn1_p, g_ffn1);
    cudaGetSymbolAddress((void**)&wqkv_h, s_wqkv_h); cudaGetSymbolAddress((void**)&wqkv_l, s_wqkv_l);
    cudaGetSymbolAddress((void**)&wo_h,   s_wo_h);   cudaGetSymbolAddress((void**)&wo_l,   s_wo_l);
    cudaGetSymbolAddress((void**)&w1_h,   s_w1_h);   cudaGetSymbolAddress((void**)&w1_l,   s_w1_l);
    cudaGetSymbolAddress((void**)&w2_h,   s_w2_h);   cudaGetSymbolAddress((void**)&w2_l,   s_w2_l);

    cudaFuncSetAttribute(mma_gemm<0>, cudaFuncAttributeMaxDynamicSharedMemorySize, SMEM_DYN);
    cudaFuncSetAttribute(mma_gemm<1>, cudaFuncAttributeMaxDynamicSharedMemorySize, SMEM_DYN);
    cudaFuncSetAttribute(mma_gemm<2>, cudaFuncAttributeMaxDynamicSharedMemorySize, SMEM_DYN);

    // 0. weight splits (fp32 -> fp16 hi/lo, once per call)
    split_kernel<<<1184, 256>>>(wqkv_w, wqkv_h, wqkv_l, 3 * DIM * DIM / 4);
    split_kernel<<<1184, 256>>>(wo_w,   wo_h,   wo_l,   DIM * DIM / 4);
    split_kernel<<<1184, 256>>>(w1_w,   w1_h,   w1_l,   INTER * DIM / 4);
    split_kernel<<<1184, 256>>>(w2_w,   w2_h,   w2_l,   DIM * INTER / 4);

    // 1. LayerNorm -> fp16 h
    ln_kernel<<<S_LEN, 256>>>(x, ln_w, ln_b);

    // 2. QKV projection
    mma_gemm<0><<<dim3(S_LEN / 128, 3 * DIM / 128), 256, SMEM_DYN>>>(
        h_p, wqkv_h, wqkv_l, wqkv_b, qkv_p, nullptr, S_LEN, 3 * DIM, DIM, nullptr, nullptr);

    // 3. split + RoPE -> fp16
    prep_qkv_kernel<<<S_LEN, 256>>>(qkv_p, pos);

    // 4. tensor-core flash attention -> fp16 y
    attn_kernel<<<dim3(S_LEN / 64, N_HEAD), 128>>>(y_p);

    // 5. output projection
    mma_gemm<0><<<dim3(S_LEN / 128, DIM / 128), 256, SMEM_DYN>>>(
        y_p, wo_h, wo_l, wo_b, attn_p, nullptr, S_LEN, DIM, DIM, nullptr, nullptr);

    // 6. FFN up + gelu -> fp16 ffn1
    mma_gemm<1><<<dim3(S_LEN / 128, INTER / 128), 256, SMEM_DYN>>>(
        h_p, w1_h, w1_l, w1_b, nullptr, ffn1_p, S_LEN, INTER, DIM, nullptr, nullptr);

    // 7. FFN down + residual fuse
    mma_gemm<2><<<dim3(S_LEN / 128, DIM / 128), 256, SMEM_DYN>>>(
        ffn1_p, w2_h, w2_l, w2_b, out, nullptr, S_LEN, DIM, INTER, attn_p, x);
}